// round 4
// baseline (speedup 1.0000x reference)
#include <cuda_runtime.h>
#include <cstddef>

#define NN 50000
#define NE 800000
#define DD 128
#define NSTEPS 5
#define EPSF 1e-5f

// ---------------- scratch (static __device__ — no allocation) ----------------
static __device__ float g_hn  [NN*DD];
static __device__ float g_h   [NN*DD];
static __device__ float g_x   [NN*DD];
static __device__ float g_acc [NN*DD];
static __device__ float g_cnt [NN];
static __device__ float g_deg [NN];
static __device__ float g_dis [NN];
static __device__ float g_selfw[NN];
static __device__ float g_coef[NE];
static __device__ float g_bnsum[DD];
static __device__ float g_bnsq [DD];

// ---------------- helpers ----------------
__device__ __forceinline__ void red_add_v4(float* p, float a, float b, float c, float d){
    asm volatile("red.global.add.v4.f32 [%0], {%1,%2,%3,%4};"
                 :: "l"(p), "f"(a), "f"(b), "f"(c), "f"(d) : "memory");
}

// one 64x128 output tile, K = kdim, activations in smem (stride `stride`),
// weights in smem sW laid out [k][c] row-major 128 wide.
// thread owns (row = tid>>2, cols col0..col0+31)
__device__ __forceinline__ void gemm_accum(const float* __restrict__ bufX, int stride, int kdim,
                                           const float* __restrict__ sW, int col0, int row,
                                           float acc[32]){
#pragma unroll
    for (int j=0;j<32;j++) acc[j]=0.f;
    for (int k=0;k<kdim;k++){
        float a = bufX[row*stride+k];
        const float4* w = reinterpret_cast<const float4*>(sW + k*DD + col0);
#pragma unroll
        for (int j=0;j<8;j++){
            float4 wv = w[j];
            acc[4*j+0] += a*wv.x;
            acc[4*j+1] += a*wv.y;
            acc[4*j+2] += a*wv.z;
            acc[4*j+3] += a*wv.w;
        }
    }
}

// ---------------- fused 3-layer MLP (+LayerNorm) ----------------
// MODE 0: node encoder  -> store rows to out
// MODE 1: edge encoder  -> LN then atomic scatter-add to out[src], count to cnt
// MODE 2: decoder       -> input is [nrows,128] global, store rows to out
template<int INDIM, int MODE>
__global__ void __launch_bounds__(256,1)
mlp3_kernel(const float* __restrict__ in,
            const float* __restrict__ W1, const float* __restrict__ b1,
            const float* __restrict__ W2, const float* __restrict__ b2,
            const float* __restrict__ W3, const float* __restrict__ b3,
            const float* __restrict__ lng, const float* __restrict__ lnb,
            const int* __restrict__ srcIdx,
            float* __restrict__ out, float* __restrict__ cnt, int nrows)
{
    extern __shared__ float sm[];
    float* sW   = sm;              // 16384
    float* bufA = sm + 16384;      // 64*132 = 8448
    float* bufB = bufA + 8448;     // 8448
    float* sIn  = bufB + 8448;     // 1536
    float* sG   = sIn + 1536;      // 128
    float* sBt  = sG + 128;        // 128
    float* sBias= sBt + 128;       // 128
    int*   sSrc = (int*)(sBias + 128); // 64

    const int t    = threadIdx.x;
    const int row  = t >> 2;
    const int col0 = (t & 3) * 32;
    const int row0 = blockIdx.x * 64;
    constexpr int INPAD = (INDIM==19) ? 20 : (INDIM==4 ? 5 : 132);

    if (t < 128){ sG[t] = lng[t]; sBt[t] = lnb[t]; }

    if constexpr (MODE == 2){
        for (int i = t; i < 64*128; i += 256){
            int r = i >> 7, k = i & 127;
            float v = (row0 + r < nrows) ? in[(size_t)(row0+r)*128 + k] : 0.f;
            bufB[r*132 + k] = v;
        }
    } else {
        for (int i = t; i < 64*INDIM; i += 256){
            int r = i / INDIM, k = i - r*INDIM;
            float v = (row0 + r < nrows) ? in[(size_t)(row0+r)*INDIM + k] : 0.f;
            sIn[r*INPAD + k] = v;
        }
    }
    if constexpr (MODE == 1){
        if (t < 64) sSrc[t] = srcIdx[row0 + t];
    }
    for (int i = t*4; i < INDIM*128; i += 1024)
        *reinterpret_cast<float4*>(sW+i) = *reinterpret_cast<const float4*>(W1+i);
    if (t < 128) sBias[t] = b1[t];
    __syncthreads();

    float acc[32];
    // layer 1 (+leaky)
    if constexpr (MODE == 2) gemm_accum(bufB, 132, 128, sW, col0, row, acc);
    else                     gemm_accum(sIn, INPAD, INDIM, sW, col0, row, acc);
#pragma unroll
    for (int j=0;j<32;j++){
        float v = acc[j] + sBias[col0+j];
        bufA[row*132 + col0 + j] = (v > 0.f) ? v : 0.05f*v;
    }
    __syncthreads();
    for (int i = t*4; i < 128*128; i += 1024)
        *reinterpret_cast<float4*>(sW+i) = *reinterpret_cast<const float4*>(W2+i);
    if (t < 128) sBias[t] = b2[t];
    __syncthreads();
    // layer 2 (+leaky)
    gemm_accum(bufA, 132, 128, sW, col0, row, acc);
#pragma unroll
    for (int j=0;j<32;j++){
        float v = acc[j] + sBias[col0+j];
        bufB[row*132 + col0 + j] = (v > 0.f) ? v : 0.05f*v;
    }
    __syncthreads();
    for (int i = t*4; i < 128*128; i += 1024)
        *reinterpret_cast<float4*>(sW+i) = *reinterpret_cast<const float4*>(W3+i);
    if (t < 128) sBias[t] = b3[t];
    __syncthreads();
    // layer 3 (linear)
    gemm_accum(bufB, 132, 128, sW, col0, row, acc);

    // LayerNorm over 128 cols: quad (4 threads share a row) reduction via shfl
    float sum=0.f, sq=0.f;
#pragma unroll
    for (int j=0;j<32;j++){
        float v = acc[j] + sBias[col0+j];
        acc[j] = v; sum += v; sq += v*v;
    }
    sum += __shfl_xor_sync(0xffffffffu, sum, 1);
    sum += __shfl_xor_sync(0xffffffffu, sum, 2);
    sq  += __shfl_xor_sync(0xffffffffu, sq, 1);
    sq  += __shfl_xor_sync(0xffffffffu, sq, 2);
    float m   = sum * (1.f/128.f);
    float var = sq  * (1.f/128.f) - m*m;
    float rs  = rsqrtf(var + EPSF);
#pragma unroll
    for (int j=0;j<32;j++){
        int c = col0 + j;
        acc[j] = (acc[j]-m)*rs*sG[c] + sBt[c];
    }

    if constexpr (MODE == 1){
        int s = sSrc[row];
        float* p = out + (size_t)s*128 + col0;
#pragma unroll
        for (int j=0;j<8;j++)
            red_add_v4(p + 4*j, acc[4*j], acc[4*j+1], acc[4*j+2], acc[4*j+3]);
        if ((t & 3) == 0) atomicAdd(&cnt[s], 1.0f);
    } else {
        if (row0 + row < nrows){
            float4* p = reinterpret_cast<float4*>(out + (size_t)(row0+row)*128 + col0);
#pragma unroll
            for (int j=0;j<8;j++)
                p[j] = make_float4(acc[4*j],acc[4*j+1],acc[4*j+2],acc[4*j+3]);
        }
    }
}

// ---------------- single GEMM [nrows,128]@[128,128], optional fused BatchNorm on input ----------------
__global__ void __launch_bounds__(256,2)
gemm_kernel(const float* __restrict__ in, const float* __restrict__ W,
            float* __restrict__ out, int nrows,
            const float* __restrict__ bnsum, const float* __restrict__ bnsq,
            const float* __restrict__ bng, const float* __restrict__ bnb, int useBN)
{
    extern __shared__ float sm[];
    float* sW     = sm;             // 16384
    float* bufA   = sm + 16384;     // 8448
    float* sScale = bufA + 8448;    // 128
    float* sShift = sScale + 128;   // 128

    const int t    = threadIdx.x;
    const int row  = t >> 2;
    const int col0 = (t & 3) * 32;
    const int row0 = blockIdx.x * 64;

    if (useBN && t < 128){
        float mm = bnsum[t] * (1.f/NN);
        float vv = bnsq[t]  * (1.f/NN) - mm*mm;
        float rr = rsqrtf(vv + EPSF);
        sScale[t] = rr * bng[t];
        sShift[t] = bnb[t] - mm * rr * bng[t];
    }
    __syncthreads();

    for (int i = t; i < 64*128; i += 256){
        int r = i >> 7, k = i & 127;
        float v = (row0 + r < nrows) ? in[(size_t)(row0+r)*128 + k] : 0.f;
        if (useBN) v = v * sScale[k] + sShift[k];
        bufA[r*132 + k] = v;
    }
    for (int i = t*4; i < 128*128; i += 1024)
        *reinterpret_cast<float4*>(sW+i) = *reinterpret_cast<const float4*>(W+i);
    __syncthreads();

    float acc[32];
    gemm_accum(bufA, 132, 128, sW, col0, row, acc);

    if (row0 + row < nrows){
        float4* p = reinterpret_cast<float4*>(out + (size_t)(row0+row)*128 + col0);
#pragma unroll
        for (int j=0;j<8;j++)
            p[j] = make_float4(acc[4*j],acc[4*j+1],acc[4*j+2],acc[4*j+3]);
    }
}

// ---------------- edge scatter: acc[dst] += h[src] * coef[e] ----------------
__global__ void __launch_bounds__(256)
scatter_kernel(const float* __restrict__ h, const int* __restrict__ src,
               const int* __restrict__ dst, const float* __restrict__ coef,
               float* __restrict__ acc)
{
    int idx = blockIdx.x * 256 + threadIdx.x;
    int e = idx >> 5;
    if (e >= NE) return;
    int q = (idx & 31) * 4;
    int s = __ldg(src + e), d = __ldg(dst + e);
    float c = __ldg(coef + e);
    float4 v = *reinterpret_cast<const float4*>(h + (size_t)s*128 + q);
    red_add_v4(acc + (size_t)d*128 + q, v.x*c, v.y*c, v.z*c, v.w*c);
}

// ---------------- small elementwise / reduction kernels ----------------
__global__ void deg_kernel(const int* __restrict__ dst, float* __restrict__ deg){
    int e = blockIdx.x*256 + threadIdx.x;
    if (e < NE) atomicAdd(&deg[dst[e]], 1.0f);
}
__global__ void nodeprep_kernel(float* __restrict__ deg, float* __restrict__ dis, float* __restrict__ selfw){
    int n = blockIdx.x*256 + threadIdx.x;
    if (n < NN){
        float d = deg[n] + 1.0f;
        dis[n] = rsqrtf(d);
        selfw[n] = 1.0f/d;
    }
}
__global__ void coef_kernel(const int* __restrict__ src, const int* __restrict__ dst,
                            const float* __restrict__ dis, float* __restrict__ coef){
    int e = blockIdx.x*256 + threadIdx.x;
    if (e < NE) coef[e] = dis[src[e]] * dis[dst[e]];
}
// hn += acc / max(cnt,1)
__global__ void encfin_kernel(float* __restrict__ hn, const float* __restrict__ acc,
                              const float* __restrict__ cnt){
    int i4 = blockIdx.x*256 + threadIdx.x;   // float4 index
    if (i4 >= NN*32) return;
    int n = i4 >> 5;
    float inv = 1.0f / fmaxf(cnt[n], 1.0f);
    float4 a = reinterpret_cast<const float4*>(acc)[i4];
    float4 hh = reinterpret_cast<float4*>(hn)[i4];
    hh.x += a.x*inv; hh.y += a.y*inv; hh.z += a.z*inv; hh.w += a.w*inv;
    reinterpret_cast<float4*>(hn)[i4] = hh;
}
// x = leaky(acc + h*selfw + b);  + per-channel BN stats accumulation
__global__ void __launch_bounds__(256)
epi1_kernel(const float* __restrict__ h, const float* __restrict__ acc,
            const float* __restrict__ selfw, const float* __restrict__ bias,
            float* __restrict__ x, float* __restrict__ bnsum, float* __restrict__ bnsq)
{
    __shared__ float r1[256], r2[256];
    int t = threadIdx.x;
    int c = t & 127;
    float s = 0.f, s2 = 0.f;
    float b = bias[c];
    for (long long i = (long long)blockIdx.x*256 + t; i < (long long)NN*128; i += (long long)gridDim.x*256){
        int n = (int)(i >> 7);
        float v = acc[i] + h[i]*selfw[n] + b;
        v = (v > 0.f) ? v : 0.05f*v;
        x[i] = v;
        s += v; s2 += v*v;
    }
    r1[t] = s; r2[t] = s2;
    __syncthreads();
    if (t < 128){
        atomicAdd(&bnsum[t], r1[t] + r1[t+128]);
        atomicAdd(&bnsq[t],  r2[t] + r2[t+128]);
    }
}
// hn += acc + h*selfw + b
__global__ void epi2_kernel(const float* __restrict__ h, const float* __restrict__ acc,
                            const float* __restrict__ selfw, const float* __restrict__ bias,
                            float* __restrict__ hn)
{
    int i4 = blockIdx.x*256 + threadIdx.x;
    if (i4 >= NN*32) return;
    int n = i4 >> 5;
    int c0 = (i4 & 31) * 4;
    float sw = selfw[n];
    float4 a  = reinterpret_cast<const float4*>(acc)[i4];
    float4 hv = reinterpret_cast<const float4*>(h)[i4];
    float4 b4 = *reinterpret_cast<const float4*>(bias + c0);
    float4 o  = reinterpret_cast<float4*>(hn)[i4];
    o.x += a.x + hv.x*sw + b4.x;
    o.y += a.y + hv.y*sw + b4.y;
    o.z += a.z + hv.z*sw + b4.z;
    o.w += a.w + hv.w*sw + b4.w;
    reinterpret_cast<float4*>(hn)[i4] = o;
}

// ---------------- launcher ----------------
extern "C" void kernel_launch(void* const* d_in, const int* in_sizes, int n_in,
                              void* d_out, int out_size)
{
    const float* node_feat = (const float*)d_in[0];
    const float* edge_feat = (const float*)d_in[1];
    const int*   edge_index= (const int*)  d_in[2];
    const float* enW1=(const float*)d_in[3],  *enb1=(const float*)d_in[4];
    const float* enW2=(const float*)d_in[5],  *enb2=(const float*)d_in[6];
    const float* enW3=(const float*)d_in[7],  *enb3=(const float*)d_in[8];
    const float* enlg=(const float*)d_in[9],  *enlb=(const float*)d_in[10];
    const float* eeW1=(const float*)d_in[11], *eeb1=(const float*)d_in[12];
    const float* eeW2=(const float*)d_in[13], *eeb2=(const float*)d_in[14];
    const float* eeW3=(const float*)d_in[15], *eeb3=(const float*)d_in[16];
    const float* eelg=(const float*)d_in[17], *eelb=(const float*)d_in[18];
    const float* procW=(const float*)d_in[19], *procb=(const float*)d_in[20];
    const float* bng =(const float*)d_in[21], *bnb =(const float*)d_in[22];
    const float* dW1=(const float*)d_in[23], *db1=(const float*)d_in[24];
    const float* dW2=(const float*)d_in[25], *db2=(const float*)d_in[26];
    const float* dW3=(const float*)d_in[27], *db3=(const float*)d_in[28];
    const float* dlg=(const float*)d_in[29], *dlb=(const float*)d_in[30];
    float* out = (float*)d_out;

    const int* src = edge_index;
    const int* dst = edge_index + NE;

    float *p_hn,*p_h,*p_x,*p_acc,*p_cnt,*p_deg,*p_dis,*p_selfw,*p_coef,*p_bnsum,*p_bnsq;
    cudaGetSymbolAddress((void**)&p_hn,   g_hn);
    cudaGetSymbolAddress((void**)&p_h,    g_h);
    cudaGetSymbolAddress((void**)&p_x,    g_x);
    cudaGetSymbolAddress((void**)&p_acc,  g_acc);
    cudaGetSymbolAddress((void**)&p_cnt,  g_cnt);
    cudaGetSymbolAddress((void**)&p_deg,  g_deg);
    cudaGetSymbolAddress((void**)&p_dis,  g_dis);
    cudaGetSymbolAddress((void**)&p_selfw,g_selfw);
    cudaGetSymbolAddress((void**)&p_coef, g_coef);
    cudaGetSymbolAddress((void**)&p_bnsum,g_bnsum);
    cudaGetSymbolAddress((void**)&p_bnsq, g_bnsq);

    const size_t MLP_SMEM  = (size_t)(16384 + 8448 + 8448 + 1536 + 128 + 128 + 128 + 64) * 4;
    const size_t GEMM_SMEM = (size_t)(16384 + 8448 + 128 + 128) * 4;
    cudaFuncSetAttribute(mlp3_kernel<19,0>, cudaFuncAttributeMaxDynamicSharedMemorySize, (int)MLP_SMEM);
    cudaFuncSetAttribute(mlp3_kernel<4,1>,  cudaFuncAttributeMaxDynamicSharedMemorySize, (int)MLP_SMEM);
    cudaFuncSetAttribute(mlp3_kernel<128,2>,cudaFuncAttributeMaxDynamicSharedMemorySize, (int)MLP_SMEM);
    cudaFuncSetAttribute(gemm_kernel,       cudaFuncAttributeMaxDynamicSharedMemorySize, (int)GEMM_SMEM);

    const int NODE_TB = (NN + 63) / 64;        // 782
    const int EDGE_TB = NE / 64;               // 12500
    const int E_THREADS_B = (NE + 255) / 256;  // 3125
    const int N_THREADS_B = (NN + 255) / 256;  // 196
    const int EW_B = (NE*32) / 256;            // 100000
    const int NV4_B = (NN*32 + 255) / 256;     // 6250

    // --- init scratch ---
    cudaMemsetAsync(p_acc, 0, (size_t)NN*DD*sizeof(float));
    cudaMemsetAsync(p_cnt, 0, (size_t)NN*sizeof(float));
    cudaMemsetAsync(p_deg, 0, (size_t)NN*sizeof(float));

    // --- encoders ---
    mlp3_kernel<19,0><<<NODE_TB,256,MLP_SMEM>>>(node_feat, enW1,enb1,enW2,enb2,enW3,enb3,
                                                enlg,enlb, nullptr, p_hn, nullptr, NN);
    mlp3_kernel<4,1><<<EDGE_TB,256,MLP_SMEM>>>(edge_feat, eeW1,eeb1,eeW2,eeb2,eeW3,eeb3,
                                               eelg,eelb, src, p_acc, p_cnt, NE);
    deg_kernel<<<E_THREADS_B,256>>>(dst, p_deg);
    encfin_kernel<<<NV4_B,256>>>(p_hn, p_acc, p_cnt);
    nodeprep_kernel<<<N_THREADS_B,256>>>(p_deg, p_dis, p_selfw);
    coef_kernel<<<E_THREADS_B,256>>>(src, dst, p_dis, p_coef);

    // --- 5 processor steps ---
    for (int s = 0; s < NSTEPS; s++){
        const float* W0 = procW + (size_t)(s*2+0)*DD*DD;
        const float* W1 = procW + (size_t)(s*2+1)*DD*DD;
        const float* b0 = procb + (size_t)(s*2+0)*DD;
        const float* b1 = procb + (size_t)(s*2+1)*DD;

        // conv1: h = hn @ W0
        gemm_kernel<<<NODE_TB,256,GEMM_SMEM>>>(p_hn, W0, p_h, NN, nullptr,nullptr,nullptr,nullptr, 0);
        cudaMemsetAsync(p_acc, 0, (size_t)NN*DD*sizeof(float));
        scatter_kernel<<<EW_B,256>>>(p_h, src, dst, p_coef, p_acc);
        cudaMemsetAsync(p_bnsum, 0, DD*sizeof(float));
        cudaMemsetAsync(p_bnsq,  0, DD*sizeof(float));
        epi1_kernel<<<1184,256>>>(p_h, p_acc, p_selfw, b0, p_x, p_bnsum, p_bnsq);

        // conv2: h = BN(x) @ W1  (BN folded into GEMM input load)
        gemm_kernel<<<NODE_TB,256,GEMM_SMEM>>>(p_x, W1, p_h, NN, p_bnsum, p_bnsq,
                                               bng + (size_t)s*DD, bnb + (size_t)s*DD, 1);
        cudaMemsetAsync(p_acc, 0, (size_t)NN*DD*sizeof(float));
        scatter_kernel<<<EW_B,256>>>(p_h, src, dst, p_coef, p_acc);
        epi2_kernel<<<NV4_B,256>>>(p_h, p_acc, p_selfw, b1, p_hn);
    }

    // --- decoder ---
    mlp3_kernel<128,2><<<NODE_TB,256,MLP_SMEM>>>(p_hn, dW1,db1,dW2,db2,dW3,db3,
                                                 dlg,dlb, nullptr, out, nullptr, NN);
    (void)in_sizes; (void)n_in; (void)out_size;
}

// round 6
// speedup vs baseline: 5.9970x; 5.9970x over previous
#include <cuda_runtime.h>
#include <cstddef>

#define NN 50000
#define NE 800000
#define DD 128
#define NSTEPS 5
#define EPSF 1e-5f

// ---------------- scratch (static __device__ — no allocation) ----------------
static __device__ float g_hn  [NN*DD];
static __device__ float g_h   [NN*DD];
static __device__ float g_x   [NN*DD];
static __device__ float g_eacc[NN*DD];
static __device__ int   g_cnt [NN];       // edges per src (encoder mean)
static __device__ int   g_deg [NN];       // edges per dst (GCN degree)
static __device__ float g_dis [NN];
static __device__ float g_selfw[NN];
static __device__ int   g_off [NN+1];     // CSR offsets by dst
static __device__ int   g_cur [NN];
static __device__ int   g_csrc[NE];       // CSR: src per slot
static __device__ float g_ccoef[NE];      // CSR: coef per slot
static __device__ float g_bnsum[DD];
static __device__ float g_bnsq [DD];

// ---------------- helpers ----------------
__device__ __forceinline__ void red_add_v4(float* p, float a, float b, float c, float d){
    asm volatile("red.global.add.v4.f32 [%0], {%1,%2,%3,%4};"
                 :: "l"(p), "f"(a), "f"(b), "f"(c), "f"(d) : "memory");
}

// Conflict-free 64x128 tile GEMM core.
// Mapping: warp (t>>5) owns rows warp*8..warp*8+7; lane owns cols lane*4..lane*4+3.
// Weight LDS.128: lanes read CONSECUTIVE float4 -> conflict-free.
// Activation loads: warp-uniform broadcast -> no conflict.
template<int KDIM>
__device__ __forceinline__ void gemm_core(const float* __restrict__ xrow, int stride,
                                          const float* __restrict__ sW, int lane,
                                          float acc[8][4])
{
#pragma unroll
    for (int r=0;r<8;r++){ acc[r][0]=0.f; acc[r][1]=0.f; acc[r][2]=0.f; acc[r][3]=0.f; }
#pragma unroll 4
    for (int k=0;k<KDIM;k++){
        float4 wv = reinterpret_cast<const float4*>(sW + k*DD)[lane];
        float a[8];
#pragma unroll
        for (int r=0;r<8;r++) a[r] = xrow[r*stride + k];
#pragma unroll
        for (int r=0;r<8;r++){
            acc[r][0] += a[r]*wv.x;
            acc[r][1] += a[r]*wv.y;
            acc[r][2] += a[r]*wv.z;
            acc[r][3] += a[r]*wv.w;
        }
    }
}

// ---------------- fused 3-layer MLP (+LayerNorm) ----------------
// MODE 0: node encoder -> store rows; MODE 1: edge encoder -> LN + red-scatter to out[src];
// MODE 2: decoder -> [nrows,128] input, store rows.
template<int INDIM, int MODE>
__global__ void __launch_bounds__(256,1)
mlp3_kernel(const float* __restrict__ in,
            const float* __restrict__ W1, const float* __restrict__ b1,
            const float* __restrict__ W2, const float* __restrict__ b2,
            const float* __restrict__ W3, const float* __restrict__ b3,
            const float* __restrict__ lng, const float* __restrict__ lnb,
            const int* __restrict__ srcIdx,
            float* __restrict__ out, int nrows)
{
    extern __shared__ float sm[];
    float* sW   = sm;               // 16384
    float* bufA = sm + 16384;       // 64*132
    float* bufB = bufA + 8448;      // 64*132
    float* sIn  = bufB + 8448;      // up to 64*21
    float* sG   = sIn + 1344;       // 128
    float* sBt  = sG + 128;         // 128
    float* sBias= sBt + 128;        // 128
    int*   sSrc = (int*)(sBias + 128); // 64 ints

    const int t    = threadIdx.x;
    const int lane = t & 31;
    const int warp = t >> 5;
    const int row0 = blockIdx.x * 64;
    constexpr int INPAD = (INDIM==19) ? 21 : (INDIM==4 ? 5 : 132);

    if (t < 128){ sG[t]=lng[t]; sBt[t]=lnb[t]; sBias[t]=b1[t]; }

    if constexpr (MODE == 2){
        for (int i=t;i<64*128;i+=256){
            int r=i>>7,k=i&127;
            bufB[r*132+k] = (row0+r<nrows) ? in[(size_t)(row0+r)*128+k] : 0.f;
        }
    } else {
        for (int i=t;i<64*INDIM;i+=256){
            int r=i/INDIM,k=i-r*INDIM;
            sIn[r*INPAD+k] = (row0+r<nrows) ? in[(size_t)(row0+r)*INDIM+k] : 0.f;
        }
    }
    if constexpr (MODE == 1){ if (t<64) sSrc[t]=srcIdx[row0+t]; }
    for (int i=t*4;i<INDIM*128;i+=1024)
        *reinterpret_cast<float4*>(sW+i) = *reinterpret_cast<const float4*>(W1+i);
    __syncthreads();

    float acc[8][4];
    // ---- layer 1 (+leaky) ----
    if constexpr (MODE == 2) gemm_core<128>(bufB + warp*8*132, 132, sW, lane, acc);
    else                     gemm_core<INDIM>(sIn + warp*8*INPAD, INPAD, sW, lane, acc);
    {
        float4 b4 = reinterpret_cast<const float4*>(sBias)[lane];
#pragma unroll
        for (int r=0;r<8;r++){
            float4 v;
            v.x = acc[r][0]+b4.x; v.x = (v.x>0.f)?v.x:0.05f*v.x;
            v.y = acc[r][1]+b4.y; v.y = (v.y>0.f)?v.y:0.05f*v.y;
            v.z = acc[r][2]+b4.z; v.z = (v.z>0.f)?v.z:0.05f*v.z;
            v.w = acc[r][3]+b4.w; v.w = (v.w>0.f)?v.w:0.05f*v.w;
            reinterpret_cast<float4*>(bufA + (warp*8+r)*132)[lane] = v;
        }
    }
    __syncthreads();
    for (int i=t*4;i<128*128;i+=1024)
        *reinterpret_cast<float4*>(sW+i) = *reinterpret_cast<const float4*>(W2+i);
    if (t<128) sBias[t]=b2[t];
    __syncthreads();

    // ---- layer 2 (+leaky) ----
    gemm_core<128>(bufA + warp*8*132, 132, sW, lane, acc);
    {
        float4 b4 = reinterpret_cast<const float4*>(sBias)[lane];
#pragma unroll
        for (int r=0;r<8;r++){
            float4 v;
            v.x = acc[r][0]+b4.x; v.x = (v.x>0.f)?v.x:0.05f*v.x;
            v.y = acc[r][1]+b4.y; v.y = (v.y>0.f)?v.y:0.05f*v.y;
            v.z = acc[r][2]+b4.z; v.z = (v.z>0.f)?v.z:0.05f*v.z;
            v.w = acc[r][3]+b4.w; v.w = (v.w>0.f)?v.w:0.05f*v.w;
            reinterpret_cast<float4*>(bufB + (warp*8+r)*132)[lane] = v;
        }
    }
    __syncthreads();
    for (int i=t*4;i<128*128;i+=1024)
        *reinterpret_cast<float4*>(sW+i) = *reinterpret_cast<const float4*>(W3+i);
    if (t<128) sBias[t]=b3[t];
    __syncthreads();

    // ---- layer 3 (linear) + LayerNorm ----
    gemm_core<128>(bufB + warp*8*132, 132, sW, lane, acc);
    {
        float4 b4 = reinterpret_cast<const float4*>(sBias)[lane];
        float4 gv = reinterpret_cast<const float4*>(sG)[lane];
        float4 bv = reinterpret_cast<const float4*>(sBt)[lane];
#pragma unroll
        for (int r=0;r<8;r++){
            acc[r][0]+=b4.x; acc[r][1]+=b4.y; acc[r][2]+=b4.z; acc[r][3]+=b4.w;
            float s = acc[r][0]+acc[r][1]+acc[r][2]+acc[r][3];
            float q = acc[r][0]*acc[r][0]+acc[r][1]*acc[r][1]+acc[r][2]*acc[r][2]+acc[r][3]*acc[r][3];
#pragma unroll
            for (int o=16;o>0;o>>=1){
                s += __shfl_xor_sync(0xffffffffu, s, o);
                q += __shfl_xor_sync(0xffffffffu, q, o);
            }
            float m   = s * (1.f/128.f);
            float var = q * (1.f/128.f) - m*m;
            float rs  = rsqrtf(var + EPSF);
            float4 o4;
            o4.x = (acc[r][0]-m)*rs*gv.x + bv.x;
            o4.y = (acc[r][1]-m)*rs*gv.y + bv.y;
            o4.z = (acc[r][2]-m)*rs*gv.z + bv.z;
            o4.w = (acc[r][3]-m)*rs*gv.w + bv.w;
            int row = warp*8 + r;
            if constexpr (MODE == 1){
                int sidx = sSrc[row];
                red_add_v4(out + (size_t)sidx*128 + lane*4, o4.x, o4.y, o4.z, o4.w);
            } else {
                if (row0 + row < nrows)
                    reinterpret_cast<float4*>(out + (size_t)(row0+row)*128)[lane] = o4;
            }
        }
    }
}

// ---------------- conv GEMM [nrows,128]@[128,128], optional fused BN on input ----------------
__global__ void __launch_bounds__(256,2)
gemm_kernel(const float* __restrict__ in, const float* __restrict__ W,
            float* __restrict__ out, int nrows,
            const float* __restrict__ bnsum, const float* __restrict__ bnsq,
            const float* __restrict__ bng, const float* __restrict__ bnb, int useBN)
{
    extern __shared__ float sm[];
    float* sW     = sm;             // 16384
    float* bufA   = sm + 16384;     // 8448
    float* sScale = bufA + 8448;    // 128
    float* sShift = sScale + 128;   // 128

    const int t    = threadIdx.x;
    const int lane = t & 31;
    const int warp = t >> 5;
    const int row0 = blockIdx.x * 64;

    if (t < 128){
        if (useBN){
            float mm = bnsum[t]*(1.f/NN);
            float vv = bnsq[t]*(1.f/NN) - mm*mm;
            float rr = rsqrtf(vv + EPSF);
            sScale[t] = rr*bng[t];
            sShift[t] = bnb[t] - mm*rr*bng[t];
        } else { sScale[t]=1.f; sShift[t]=0.f; }
    }
    __syncthreads();

    for (int i=t;i<64*128;i+=256){
        int r=i>>7,k=i&127;
        float v = (row0+r<nrows) ? in[(size_t)(row0+r)*128+k] : 0.f;
        bufA[r*132+k] = v*sScale[k] + sShift[k];
    }
    for (int i=t*4;i<128*128;i+=1024)
        *reinterpret_cast<float4*>(sW+i) = *reinterpret_cast<const float4*>(W+i);
    __syncthreads();

    float acc[8][4];
    gemm_core<128>(bufA + warp*8*132, 132, sW, lane, acc);
#pragma unroll
    for (int r=0;r<8;r++){
        int row = warp*8 + r;
        if (row0 + row < nrows)
            reinterpret_cast<float4*>(out + (size_t)(row0+row)*128)[lane] =
                make_float4(acc[r][0],acc[r][1],acc[r][2],acc[r][3]);
    }
}

// ---------------- fused CSR aggregation + epilogue (warp per node) ----------------
// MODE 1: x = leaky(agg + self + bias), accumulate BN stats
// MODE 2: hn += agg + self + bias
template<int MODE>
__global__ void __launch_bounds__(256)
agg_kernel(const float* __restrict__ h, const int* __restrict__ off,
           const int* __restrict__ csrc, const float* __restrict__ ccoef,
           const float* __restrict__ selfw, const float* __restrict__ bias,
           float* __restrict__ xout, float* __restrict__ hn,
           float* __restrict__ bnsum, float* __restrict__ bnsq)
{
    __shared__ float sbs[DD], sbq[DD];
    const int t = threadIdx.x, lane = t & 31, w = t >> 5;
    if constexpr (MODE == 1){
        if (t < 128){ sbs[t]=0.f; sbq[t]=0.f; }
        __syncthreads();
    }
    float4 b4 = reinterpret_cast<const float4*>(bias)[lane];
    float s0=0.f,s1=0.f,s2=0.f,s3=0.f,q0=0.f,q1=0.f,q2=0.f,q3=0.f;
    const int nwarps = gridDim.x * 8;

    for (int n = blockIdx.x*8 + w; n < NN; n += nwarps){
        int e0 = off[n], e1 = off[n+1];
        float ax=0.f, ay=0.f, az=0.f, aw=0.f;
        int i = e0;
        for (; i+1 < e1; i += 2){
            int   sA = csrc[i];   float cA = ccoef[i];
            int   sB = csrc[i+1]; float cB = ccoef[i+1];
            float4 vA = reinterpret_cast<const float4*>(h + (size_t)sA*DD)[lane];
            float4 vB = reinterpret_cast<const float4*>(h + (size_t)sB*DD)[lane];
            ax += vA.x*cA + vB.x*cB; ay += vA.y*cA + vB.y*cB;
            az += vA.z*cA + vB.z*cB; aw += vA.w*cA + vB.w*cB;
        }
        if (i < e1){
            int sA = csrc[i]; float cA = ccoef[i];
            float4 vA = reinterpret_cast<const float4*>(h + (size_t)sA*DD)[lane];
            ax += vA.x*cA; ay += vA.y*cA; az += vA.z*cA; aw += vA.w*cA;
        }
        float4 hv = reinterpret_cast<const float4*>(h + (size_t)n*DD)[lane];
        float sw = selfw[n];
        ax += hv.x*sw + b4.x; ay += hv.y*sw + b4.y;
        az += hv.z*sw + b4.z; aw += hv.w*sw + b4.w;
        if constexpr (MODE == 1){
            ax = (ax>0.f)?ax:0.05f*ax; ay = (ay>0.f)?ay:0.05f*ay;
            az = (az>0.f)?az:0.05f*az; aw = (aw>0.f)?aw:0.05f*aw;
            reinterpret_cast<float4*>(xout + (size_t)n*DD)[lane] = make_float4(ax,ay,az,aw);
            s0+=ax;s1+=ay;s2+=az;s3+=aw;
            q0+=ax*ax;q1+=ay*ay;q2+=az*az;q3+=aw*aw;
        } else {
            float4 o = reinterpret_cast<float4*>(hn + (size_t)n*DD)[lane];
            o.x+=ax; o.y+=ay; o.z+=az; o.w+=aw;
            reinterpret_cast<float4*>(hn + (size_t)n*DD)[lane] = o;
        }
    }
    if constexpr (MODE == 1){
        atomicAdd(&sbs[lane*4+0],s0); atomicAdd(&sbs[lane*4+1],s1);
        atomicAdd(&sbs[lane*4+2],s2); atomicAdd(&sbs[lane*4+3],s3);
        atomicAdd(&sbq[lane*4+0],q0); atomicAdd(&sbq[lane*4+1],q1);
        atomicAdd(&sbq[lane*4+2],q2); atomicAdd(&sbq[lane*4+3],q3);
        __syncthreads();
        if (t < 128){ atomicAdd(&bnsum[t], sbs[t]); atomicAdd(&bnsq[t], sbq[t]); }
    }
}

// ---------------- prep kernels ----------------
__global__ void deg_kernel(const int* __restrict__ src, const int* __restrict__ dst,
                           int* __restrict__ degD, int* __restrict__ cntS){
    int e = blockIdx.x*256 + threadIdx.x;
    if (e < NE){ atomicAdd(&degD[dst[e]], 1); atomicAdd(&cntS[src[e]], 1); }
}
__global__ void nodeprep_kernel(const int* __restrict__ degD,
                                float* __restrict__ dis, float* __restrict__ selfw){
    int n = blockIdx.x*256 + threadIdx.x;
    if (n < NN){
        float d = (float)degD[n] + 1.0f;
        dis[n] = rsqrtf(d);
        selfw[n] = 1.0f/d;
    }
}
// single-block exclusive scan of degD -> off[0..NN]
__global__ void scan_kernel(const int* __restrict__ degD, int* __restrict__ off){
    __shared__ int sh[32];
    __shared__ int carry;
    const int t = threadIdx.x, lane = t & 31, w = t >> 5;
    if (t == 0){ carry = 0; off[0] = 0; }
    __syncthreads();
    for (int base = 0; base < NN; base += 1024){
        int i = base + t;
        int v = (i < NN) ? degD[i] : 0;
        int x = v;
#pragma unroll
        for (int o=1;o<32;o<<=1){ int y=__shfl_up_sync(0xffffffffu,x,o); if (lane>=o) x+=y; }
        if (lane == 31) sh[w] = x;
        __syncthreads();
        if (w == 0){
            int y = sh[lane];
#pragma unroll
            for (int o=1;o<32;o<<=1){ int z=__shfl_up_sync(0xffffffffu,y,o); if (lane>=o) y+=z; }
            sh[lane] = y;
        }
        __syncthreads();
        int add = (w > 0) ? sh[w-1] : 0;
        int incl = x + add + carry;
        if (i < NN) off[i+1] = incl;
        __syncthreads();
        if (t == 1023) carry = incl;
        __syncthreads();
    }
}
__global__ void fill_kernel(const int* __restrict__ src, const int* __restrict__ dst,
                            const float* __restrict__ dis, const int* __restrict__ off,
                            int* __restrict__ cur, int* __restrict__ csrc, float* __restrict__ ccoef){
    int e = blockIdx.x*256 + threadIdx.x;
    if (e < NE){
        int d = dst[e], s = src[e];
        int pos = off[d] + atomicAdd(&cur[d], 1);
        csrc[pos]  = s;
        ccoef[pos] = dis[s]*dis[d];
    }
}
// hn += eacc / max(cnt,1)
__global__ void encfin_kernel(float* __restrict__ hn, const float* __restrict__ eacc,
                              const int* __restrict__ cnt){
    int i4 = blockIdx.x*256 + threadIdx.x;
    if (i4 >= NN*32) return;
    int n = i4 >> 5;
    float inv = 1.0f / fmaxf((float)cnt[n], 1.0f);
    float4 a  = reinterpret_cast<const float4*>(eacc)[i4];
    float4 hh = reinterpret_cast<float4*>(hn)[i4];
    hh.x += a.x*inv; hh.y += a.y*inv; hh.z += a.z*inv; hh.w += a.w*inv;
    reinterpret_cast<float4*>(hn)[i4] = hh;
}

// ---------------- launcher ----------------
extern "C" void kernel_launch(void* const* d_in, const int* in_sizes, int n_in,
                              void* d_out, int out_size)
{
    const float* node_feat = (const float*)d_in[0];
    const float* edge_feat = (const float*)d_in[1];
    const int*   edge_index= (const int*)  d_in[2];
    const float* enW1=(const float*)d_in[3],  *enb1=(const float*)d_in[4];
    const float* enW2=(const float*)d_in[5],  *enb2=(const float*)d_in[6];
    const float* enW3=(const float*)d_in[7],  *enb3=(const float*)d_in[8];
    const float* enlg=(const float*)d_in[9],  *enlb=(const float*)d_in[10];
    const float* eeW1=(const float*)d_in[11], *eeb1=(const float*)d_in[12];
    const float* eeW2=(const float*)d_in[13], *eeb2=(const float*)d_in[14];
    const float* eeW3=(const float*)d_in[15], *eeb3=(const float*)d_in[16];
    const float* eelg=(const float*)d_in[17], *eelb=(const float*)d_in[18];
    const float* procW=(const float*)d_in[19], *procb=(const float*)d_in[20];
    const float* bng =(const float*)d_in[21], *bnb =(const float*)d_in[22];
    const float* dW1=(const float*)d_in[23], *db1=(const float*)d_in[24];
    const float* dW2=(const float*)d_in[25], *db2=(const float*)d_in[26];
    const float* dW3=(const float*)d_in[27], *db3=(const float*)d_in[28];
    const float* dlg=(const float*)d_in[29], *dlb=(const float*)d_in[30];
    float* out = (float*)d_out;

    const int* src = edge_index;
    const int* dst = edge_index + NE;

    float *p_hn,*p_h,*p_x,*p_eacc,*p_dis,*p_selfw,*p_ccoef,*p_bnsum,*p_bnsq;
    int *p_cnt,*p_deg,*p_off,*p_cur,*p_csrc;
    cudaGetSymbolAddress((void**)&p_hn,   g_hn);
    cudaGetSymbolAddress((void**)&p_h,    g_h);
    cudaGetSymbolAddress((void**)&p_x,    g_x);
    cudaGetSymbolAddress((void**)&p_eacc, g_eacc);
    cudaGetSymbolAddress((void**)&p_cnt,  g_cnt);
    cudaGetSymbolAddress((void**)&p_deg,  g_deg);
    cudaGetSymbolAddress((void**)&p_dis,  g_dis);
    cudaGetSymbolAddress((void**)&p_selfw,g_selfw);
    cudaGetSymbolAddress((void**)&p_off,  g_off);
    cudaGetSymbolAddress((void**)&p_cur,  g_cur);
    cudaGetSymbolAddress((void**)&p_csrc, g_csrc);
    cudaGetSymbolAddress((void**)&p_ccoef,g_ccoef);
    cudaGetSymbolAddress((void**)&p_bnsum,g_bnsum);
    cudaGetSymbolAddress((void**)&p_bnsq, g_bnsq);

    // sSrc needs 64 ints -> reserve 64 words (round-5 bug: was 16 -> smem OOB)
    const size_t MLP_SMEM  = (size_t)(16384 + 8448 + 8448 + 1344 + 128 + 128 + 128 + 64) * 4;
    const size_t GEMM_SMEM = (size_t)(16384 + 8448 + 128 + 128) * 4;
    cudaFuncSetAttribute(mlp3_kernel<19,0>, cudaFuncAttributeMaxDynamicSharedMemorySize, (int)MLP_SMEM);
    cudaFuncSetAttribute(mlp3_kernel<4,1>,  cudaFuncAttributeMaxDynamicSharedMemorySize, (int)MLP_SMEM);
    cudaFuncSetAttribute(mlp3_kernel<128,2>,cudaFuncAttributeMaxDynamicSharedMemorySize, (int)MLP_SMEM);
    cudaFuncSetAttribute(gemm_kernel,       cudaFuncAttributeMaxDynamicSharedMemorySize, (int)GEMM_SMEM);

    const int NODE_TB = (NN + 63) / 64;        // 782
    const int EDGE_TB = NE / 64;               // 12500
    const int E_B256  = (NE + 255) / 256;      // 3125
    const int N_B256  = (NN + 255) / 256;      // 196
    const int NV4_B   = (NN*32 + 255) / 256;   // 6250
    const int AGG_B   = 1184;                  // 148 SMs * 8

    // launches 1-3: memsets
    cudaMemsetAsync(p_eacc, 0, (size_t)NN*DD*sizeof(float));
    cudaMemsetAsync(p_cnt,  0, (size_t)NN*sizeof(int));
    cudaMemsetAsync(p_deg,  0, (size_t)NN*sizeof(int));
    // 4-5: degree prep
    deg_kernel<<<E_B256,256>>>(src, dst, p_deg, p_cnt);
    nodeprep_kernel<<<N_B256,256>>>(p_deg, p_dis, p_selfw);
    // 6: node encoder
    mlp3_kernel<19,0><<<NODE_TB,256,MLP_SMEM>>>(node_feat, enW1,enb1,enW2,enb2,enW3,enb3,
                                                enlg,enlb, nullptr, p_hn, NN);
    // 7: edge encoder  <-- ncu capture slot
    mlp3_kernel<4,1><<<EDGE_TB,256,MLP_SMEM>>>(edge_feat, eeW1,eeb1,eeW2,eeb2,eeW3,eeb3,
                                               eelg,eelb, src, p_eacc, NE);
    // 8: scatter-mean finalize
    encfin_kernel<<<NV4_B,256>>>(p_hn, p_eacc, p_cnt);
    // 9-11: CSR build
    cudaMemsetAsync(p_cur, 0, (size_t)NN*sizeof(int));
    scan_kernel<<<1,1024>>>(p_deg, p_off);
    fill_kernel<<<E_B256,256>>>(src, dst, p_dis, p_off, p_cur, p_csrc, p_ccoef);

    // --- 5 processor steps ---
    for (int s = 0; s < NSTEPS; s++){
        const float* W0 = procW + (size_t)(s*2+0)*DD*DD;
        const float* W1 = procW + (size_t)(s*2+1)*DD*DD;
        const float* b0 = procb + (size_t)(s*2+0)*DD;
        const float* b1 = procb + (size_t)(s*2+1)*DD;

        gemm_kernel<<<NODE_TB,256,GEMM_SMEM>>>(p_hn, W0, p_h, NN,
                                               nullptr,nullptr,nullptr,nullptr, 0);
        cudaMemsetAsync(p_bnsum, 0, DD*sizeof(float));
        cudaMemsetAsync(p_bnsq,  0, DD*sizeof(float));
        agg_kernel<1><<<AGG_B,256>>>(p_h, p_off, p_csrc, p_ccoef, p_selfw, b0,
                                     p_x, nullptr, p_bnsum, p_bnsq);

        gemm_kernel<<<NODE_TB,256,GEMM_SMEM>>>(p_x, W1, p_h, NN,
                                               p_bnsum, p_bnsq,
                                               bng + (size_t)s*DD, bnb + (size_t)s*DD, 1);
        agg_kernel<2><<<AGG_B,256>>>(p_h, p_off, p_csrc, p_ccoef, p_selfw, b1,
                                     nullptr, p_hn, nullptr, nullptr);
    }

    // --- decoder ---
    mlp3_kernel<128,2><<<NODE_TB,256,MLP_SMEM>>>(p_hn, dW1,db1,dW2,db2,dW3,db3,
                                                 dlg,dlb, nullptr, out, NN);
    (void)in_sizes; (void)n_in; (void)out_size;
}

// round 7
// speedup vs baseline: 7.3513x; 1.2258x over previous
#include <cuda_runtime.h>
#include <cstddef>

#define NN 50000
#define NE 800000
#define DD 128
#define NSTEPS 5
#define EPSF 1e-5f

typedef unsigned long long ull;

// ---------------- scratch (static __device__ — no allocation) ----------------
static __device__ float g_hn  [NN*DD];
static __device__ float g_h   [NN*DD];
static __device__ float g_x   [NN*DD];
static __device__ float g_eacc[NN*DD];
static __device__ int   g_cnt [NN];
static __device__ int   g_deg [NN];
static __device__ float g_dis [NN];
static __device__ float g_selfw[NN];
static __device__ int   g_off [NN+1];
static __device__ int   g_cur [NN];
static __device__ int   g_csrc[NE];
static __device__ float g_ccoef[NE];
static __device__ float g_bnsum[DD];
static __device__ float g_bnsq [DD];

// ---------------- helpers ----------------
__device__ __forceinline__ void red_add_v4(float* p, float a, float b, float c, float d){
    asm volatile("red.global.add.v4.f32 [%0], {%1,%2,%3,%4};"
                 :: "l"(p), "f"(a), "f"(b), "f"(c), "f"(d) : "memory");
}
__device__ __forceinline__ ull fma2(ull a, ull b, ull c){
    ull d;
    asm("fma.rn.f32x2 %0, %1, %2, %3;" : "=l"(d) : "l"(a), "l"(b), "l"(c));
    return d;
}
__device__ __forceinline__ float pairsum(ull p){
    unsigned lo, hi;
    asm("mov.b64 {%0,%1}, %2;" : "=r"(lo), "=r"(hi) : "l"(p));
    return __uint_as_float(lo) + __uint_as_float(hi);
}

// Load weights [KD][128] row-major -> k-pair interleaved smem:
// sW2[(kp*128 + c)*2 + {0,1}] = W[2kp][c], W[2kp+1][c]   (odd KD: pad 0)
template<int KD>
__device__ __forceinline__ void load_w2(const float* __restrict__ W, float* __restrict__ sW2, int t){
    constexpr int KP = (KD + 1) / 2;
    for (int i = t; i < KP*128; i += 256){
        int kp = i >> 7, c = i & 127;
        float w0 = W[(2*kp)*128 + c];
        float w1 = (2*kp+1 < KD) ? W[(2*kp+1)*128 + c] : 0.f;
        reinterpret_cast<float2*>(sW2)[i] = make_float2(w0, w1);
    }
}

// Packed-f32x2 64x128 tile GEMM core.
// warp owns rows warp*8..+7; lane owns cols lane*4..+3.
// acc2[r][c] = (sum over even k, sum over odd k) packed.
template<int KPAIRS>
__device__ __forceinline__ void gemm_core2(const float* __restrict__ xrow, int stride,
                                           const float* __restrict__ sW2, int lane,
                                           ull acc2[8][4])
{
#pragma unroll
    for (int r=0;r<8;r++){ acc2[r][0]=0ull; acc2[r][1]=0ull; acc2[r][2]=0ull; acc2[r][3]=0ull; }
#pragma unroll 2
    for (int kp=0; kp<KPAIRS; kp++){
        const ulonglong2* wp = reinterpret_cast<const ulonglong2*>(sW2 + kp*256);
        ulonglong2 wA = wp[lane*2+0];     // cols lane*4+0, lane*4+1
        ulonglong2 wB = wp[lane*2+1];     // cols lane*4+2, lane*4+3
        ull a[8];
#pragma unroll
        for (int r=0;r<8;r++)
            a[r] = *reinterpret_cast<const ull*>(xrow + r*stride + kp*2);
#pragma unroll
        for (int r=0;r<8;r++){
            acc2[r][0] = fma2(a[r], wA.x, acc2[r][0]);
            acc2[r][1] = fma2(a[r], wA.y, acc2[r][1]);
            acc2[r][2] = fma2(a[r], wB.x, acc2[r][2]);
            acc2[r][3] = fma2(a[r], wB.y, acc2[r][3]);
        }
    }
}

// ---------------- fused 3-layer MLP (+LayerNorm), in-place activation buffer ----------------
// MODE 0: node encoder -> store rows; MODE 1: edge encoder -> LN + red-scatter to out[src];
// MODE 2: decoder -> [nrows,128] input, store rows.
template<int INDIM, int MODE>
__global__ void __launch_bounds__(256,2)
mlp3_kernel(const float* __restrict__ in,
            const float* __restrict__ W1, const float* __restrict__ b1,
            const float* __restrict__ W2, const float* __restrict__ b2,
            const float* __restrict__ W3, const float* __restrict__ b3,
            const float* __restrict__ lng, const float* __restrict__ lnb,
            const int* __restrict__ srcIdx,
            float* __restrict__ out, int nrows)
{
    extern __shared__ float sm[];
    float* sW2  = sm;               // 16384
    float* buf  = sm + 16384;       // 64*132 = 8448
    float* sIn  = buf + 8448;       // 64*20 = 1280
    float* sG   = sIn + 1280;       // 128
    float* sBt  = sG + 128;         // 128
    float* sBias= sBt + 128;        // 128
    int*   sSrc = (int*)(sBias + 128); // 64 ints

    const int t    = threadIdx.x;
    const int lane = t & 31;
    const int warp = t >> 5;
    const int row0 = blockIdx.x * 64;
    constexpr int INPAD = (INDIM==19) ? 20 : (INDIM==4 ? 4 : 132);  // even for b64 loads

    if (t < 128){ sG[t]=lng[t]; sBt[t]=lnb[t]; sBias[t]=b1[t]; }

    if constexpr (MODE == 2){
        for (int i=t;i<64*32;i+=256){
            int r=i>>5, c4=i&31;
            float4 v = (row0+r<nrows) ? reinterpret_cast<const float4*>(in + (size_t)(row0+r)*128)[c4]
                                      : make_float4(0.f,0.f,0.f,0.f);
            reinterpret_cast<float4*>(buf + r*132)[c4] = v;
        }
    } else {
        for (int i=t;i<64*INPAD;i+=256){
            int r=i/INPAD, k=i-r*INPAD;
            sIn[i] = (k < INDIM && row0+r < nrows) ? in[(size_t)(row0+r)*INDIM+k] : 0.f;
        }
    }
    if constexpr (MODE == 1){ if (t<64) sSrc[t]=srcIdx[row0+t]; }
    load_w2<INDIM>(W1, sW2, t);
    __syncthreads();

    ull acc2[8][4];
    float acc[8][4];
    const float* myrows = (MODE==2) ? (buf + warp*8*132) : (sIn + warp*8*INPAD);
    const int mystride  = (MODE==2) ? 132 : INPAD;

    // ---- layer 1 (+leaky) -> buf (in-place safe: warp-private rows) ----
    gemm_core2<(INDIM+1)/2>(myrows, mystride, sW2, lane, acc2);
    {
        float4 b4 = reinterpret_cast<const float4*>(sBias)[lane];
#pragma unroll
        for (int r=0;r<8;r++){
            float4 v;
            v.x = pairsum(acc2[r][0])+b4.x; v.x=(v.x>0.f)?v.x:0.05f*v.x;
            v.y = pairsum(acc2[r][1])+b4.y; v.y=(v.y>0.f)?v.y:0.05f*v.y;
            v.z = pairsum(acc2[r][2])+b4.z; v.z=(v.z>0.f)?v.z:0.05f*v.z;
            v.w = pairsum(acc2[r][3])+b4.w; v.w=(v.w>0.f)?v.w:0.05f*v.w;
            reinterpret_cast<float4*>(buf + (warp*8+r)*132)[lane] = v;
        }
    }
    __syncthreads();
    load_w2<128>(W2, sW2, t);
    if (t<128) sBias[t]=b2[t];
    __syncthreads();

    // ---- layer 2 (+leaky), in-place ----
    gemm_core2<64>(buf + warp*8*132, 132, sW2, lane, acc2);
    {
        float4 b4 = reinterpret_cast<const float4*>(sBias)[lane];
#pragma unroll
        for (int r=0;r<8;r++){
            float4 v;
            v.x = pairsum(acc2[r][0])+b4.x; v.x=(v.x>0.f)?v.x:0.05f*v.x;
            v.y = pairsum(acc2[r][1])+b4.y; v.y=(v.y>0.f)?v.y:0.05f*v.y;
            v.z = pairsum(acc2[r][2])+b4.z; v.z=(v.z>0.f)?v.z:0.05f*v.z;
            v.w = pairsum(acc2[r][3])+b4.w; v.w=(v.w>0.f)?v.w:0.05f*v.w;
            reinterpret_cast<float4*>(buf + (warp*8+r)*132)[lane] = v;
        }
    }
    __syncthreads();
    load_w2<128>(W3, sW2, t);
    if (t<128) sBias[t]=b3[t];
    __syncthreads();

    // ---- layer 3 (linear) + LayerNorm ----
    gemm_core2<64>(buf + warp*8*132, 132, sW2, lane, acc2);
    {
        float4 b4 = reinterpret_cast<const float4*>(sBias)[lane];
        float4 gv = reinterpret_cast<const float4*>(sG)[lane];
        float4 bv = reinterpret_cast<const float4*>(sBt)[lane];
#pragma unroll
        for (int r=0;r<8;r++){
            acc[r][0]=pairsum(acc2[r][0])+b4.x; acc[r][1]=pairsum(acc2[r][1])+b4.y;
            acc[r][2]=pairsum(acc2[r][2])+b4.z; acc[r][3]=pairsum(acc2[r][3])+b4.w;
            float s = acc[r][0]+acc[r][1]+acc[r][2]+acc[r][3];
            float q = acc[r][0]*acc[r][0]+acc[r][1]*acc[r][1]+acc[r][2]*acc[r][2]+acc[r][3]*acc[r][3];
#pragma unroll
            for (int o=16;o>0;o>>=1){
                s += __shfl_xor_sync(0xffffffffu, s, o);
                q += __shfl_xor_sync(0xffffffffu, q, o);
            }
            float m   = s * (1.f/128.f);
            float var = q * (1.f/128.f) - m*m;
            float rs  = rsqrtf(var + EPSF);
            float4 o4;
            o4.x = (acc[r][0]-m)*rs*gv.x + bv.x;
            o4.y = (acc[r][1]-m)*rs*gv.y + bv.y;
            o4.z = (acc[r][2]-m)*rs*gv.z + bv.z;
            o4.w = (acc[r][3]-m)*rs*gv.w + bv.w;
            int row = warp*8 + r;
            if constexpr (MODE == 1){
                int sidx = sSrc[row];
                red_add_v4(out + (size_t)sidx*128 + lane*4, o4.x, o4.y, o4.z, o4.w);
            } else {
                if (row0 + row < nrows)
                    reinterpret_cast<float4*>(out + (size_t)(row0+row)*128)[lane] = o4;
            }
        }
    }
}

// ---------------- conv GEMM [nrows,128]@[128,128], optional fused BN on input ----------------
__global__ void __launch_bounds__(256,2)
gemm_kernel(const float* __restrict__ in, const float* __restrict__ W,
            float* __restrict__ out, int nrows,
            const float* __restrict__ bnsum, const float* __restrict__ bnsq,
            const float* __restrict__ bng, const float* __restrict__ bnb, int useBN)
{
    extern __shared__ float sm[];
    float* sW2    = sm;             // 16384
    float* buf    = sm + 16384;     // 8448
    float* sScale = buf + 8448;     // 128
    float* sShift = sScale + 128;   // 128

    const int t    = threadIdx.x;
    const int lane = t & 31;
    const int warp = t >> 5;
    const int row0 = blockIdx.x * 64;

    if (t < 128){
        if (useBN){
            float mm = bnsum[t]*(1.f/NN);
            float vv = bnsq[t]*(1.f/NN) - mm*mm;
            float rr = rsqrtf(vv + EPSF);
            sScale[t] = rr*bng[t];
            sShift[t] = bnb[t] - mm*rr*bng[t];
        } else { sScale[t]=1.f; sShift[t]=0.f; }
    }
    __syncthreads();

    for (int i=t;i<64*128;i+=256){
        int r=i>>7,k=i&127;
        float v = (row0+r<nrows) ? in[(size_t)(row0+r)*128+k] : 0.f;
        buf[r*132+k] = v*sScale[k] + sShift[k];
    }
    load_w2<128>(W, sW2, t);
    __syncthreads();

    ull acc2[8][4];
    gemm_core2<64>(buf + warp*8*132, 132, sW2, lane, acc2);
#pragma unroll
    for (int r=0;r<8;r++){
        int row = warp*8 + r;
        if (row0 + row < nrows)
            reinterpret_cast<float4*>(out + (size_t)(row0+row)*128)[lane] =
                make_float4(pairsum(acc2[r][0]),pairsum(acc2[r][1]),
                            pairsum(acc2[r][2]),pairsum(acc2[r][3]));
    }
}

// ---------------- fused CSR aggregation + epilogue (warp per node) ----------------
template<int MODE>
__global__ void __launch_bounds__(256)
agg_kernel(const float* __restrict__ h, const int* __restrict__ off,
           const int* __restrict__ csrc, const float* __restrict__ ccoef,
           const float* __restrict__ selfw, const float* __restrict__ bias,
           float* __restrict__ xout, float* __restrict__ hn,
           float* __restrict__ bnsum, float* __restrict__ bnsq)
{
    __shared__ float sbs[DD], sbq[DD];
    const int t = threadIdx.x, lane = t & 31, w = t >> 5;
    if constexpr (MODE == 1){
        if (t < 128){ sbs[t]=0.f; sbq[t]=0.f; }
        __syncthreads();
    }
    float4 b4 = reinterpret_cast<const float4*>(bias)[lane];
    float s0=0.f,s1=0.f,s2=0.f,s3=0.f,q0=0.f,q1=0.f,q2=0.f,q3=0.f;
    const int nwarps = gridDim.x * 8;

    for (int n = blockIdx.x*8 + w; n < NN; n += nwarps){
        int e0 = off[n], e1 = off[n+1];
        float ax=0.f, ay=0.f, az=0.f, aw=0.f;
        int i = e0;
        for (; i+1 < e1; i += 2){
            int   sA = csrc[i];   float cA = ccoef[i];
            int   sB = csrc[i+1]; float cB = ccoef[i+1];
            float4 vA = reinterpret_cast<const float4*>(h + (size_t)sA*DD)[lane];
            float4 vB = reinterpret_cast<const float4*>(h + (size_t)sB*DD)[lane];
            ax += vA.x*cA + vB.x*cB; ay += vA.y*cA + vB.y*cB;
            az += vA.z*cA + vB.z*cB; aw += vA.w*cA + vB.w*cB;
        }
        if (i < e1){
            int sA = csrc[i]; float cA = ccoef[i];
            float4 vA = reinterpret_cast<const float4*>(h + (size_t)sA*DD)[lane];
            ax += vA.x*cA; ay += vA.y*cA; az += vA.z*cA; aw += vA.w*cA;
        }
        float4 hv = reinterpret_cast<const float4*>(h + (size_t)n*DD)[lane];
        float sw = selfw[n];
        ax += hv.x*sw + b4.x; ay += hv.y*sw + b4.y;
        az += hv.z*sw + b4.z; aw += hv.w*sw + b4.w;
        if constexpr (MODE == 1){
            ax = (ax>0.f)?ax:0.05f*ax; ay = (ay>0.f)?ay:0.05f*ay;
            az = (az>0.f)?az:0.05f*az; aw = (aw>0.f)?aw:0.05f*aw;
            reinterpret_cast<float4*>(xout + (size_t)n*DD)[lane] = make_float4(ax,ay,az,aw);
            s0+=ax;s1+=ay;s2+=az;s3+=aw;
            q0+=ax*ax;q1+=ay*ay;q2+=az*az;q3+=aw*aw;
        } else {
            float4 o = reinterpret_cast<float4*>(hn + (size_t)n*DD)[lane];
            o.x+=ax; o.y+=ay; o.z+=az; o.w+=aw;
            reinterpret_cast<float4*>(hn + (size_t)n*DD)[lane] = o;
        }
    }
    if constexpr (MODE == 1){
        atomicAdd(&sbs[lane*4+0],s0); atomicAdd(&sbs[lane*4+1],s1);
        atomicAdd(&sbs[lane*4+2],s2); atomicAdd(&sbs[lane*4+3],s3);
        atomicAdd(&sbq[lane*4+0],q0); atomicAdd(&sbq[lane*4+1],q1);
        atomicAdd(&sbq[lane*4+2],q2); atomicAdd(&sbq[lane*4+3],q3);
        __syncthreads();
        if (t < 128){ atomicAdd(&bnsum[t], sbs[t]); atomicAdd(&bnsq[t], sbq[t]); }
    }
}

// ---------------- prep kernels ----------------
__global__ void deg_kernel(const int* __restrict__ src, const int* __restrict__ dst,
                           int* __restrict__ degD, int* __restrict__ cntS){
    int e = blockIdx.x*256 + threadIdx.x;
    if (e < NE){ atomicAdd(&degD[dst[e]], 1); atomicAdd(&cntS[src[e]], 1); }
}
__global__ void nodeprep_kernel(const int* __restrict__ degD,
                                float* __restrict__ dis, float* __restrict__ selfw){
    int n = blockIdx.x*256 + threadIdx.x;
    if (n < NN){
        float d = (float)degD[n] + 1.0f;
        dis[n] = rsqrtf(d);
        selfw[n] = 1.0f/d;
    }
}
__global__ void scan_kernel(const int* __restrict__ degD, int* __restrict__ off){
    __shared__ int sh[32];
    __shared__ int carry;
    const int t = threadIdx.x, lane = t & 31, w = t >> 5;
    if (t == 0){ carry = 0; off[0] = 0; }
    __syncthreads();
    for (int base = 0; base < NN; base += 1024){
        int i = base + t;
        int v = (i < NN) ? degD[i] : 0;
        int x = v;
#pragma unroll
        for (int o=1;o<32;o<<=1){ int y=__shfl_up_sync(0xffffffffu,x,o); if (lane>=o) x+=y; }
        if (lane == 31) sh[w] = x;
        __syncthreads();
        if (w == 0){
            int y = sh[lane];
#pragma unroll
            for (int o=1;o<32;o<<=1){ int z=__shfl_up_sync(0xffffffffu,y,o); if (lane>=o) y+=z; }
            sh[lane] = y;
        }
        __syncthreads();
        int add = (w > 0) ? sh[w-1] : 0;
        int incl = x + add + carry;
        if (i < NN) off[i+1] = incl;
        __syncthreads();
        if (t == 1023) carry = incl;
        __syncthreads();
    }
}
__global__ void fill_kernel(const int* __restrict__ src, const int* __restrict__ dst,
                            const float* __restrict__ dis, const int* __restrict__ off,
                            int* __restrict__ cur, int* __restrict__ csrc, float* __restrict__ ccoef){
    int e = blockIdx.x*256 + threadIdx.x;
    if (e < NE){
        int d = dst[e], s = src[e];
        int pos = off[d] + atomicAdd(&cur[d], 1);
        csrc[pos]  = s;
        ccoef[pos] = dis[s]*dis[d];
    }
}
__global__ void encfin_kernel(float* __restrict__ hn, const float* __restrict__ eacc,
                              const int* __restrict__ cnt){
    int i4 = blockIdx.x*256 + threadIdx.x;
    if (i4 >= NN*32) return;
    int n = i4 >> 5;
    float inv = 1.0f / fmaxf((float)cnt[n], 1.0f);
    float4 a  = reinterpret_cast<const float4*>(eacc)[i4];
    float4 hh = reinterpret_cast<float4*>(hn)[i4];
    hh.x += a.x*inv; hh.y += a.y*inv; hh.z += a.z*inv; hh.w += a.w*inv;
    reinterpret_cast<float4*>(hn)[i4] = hh;
}

// ---------------- launcher ----------------
extern "C" void kernel_launch(void* const* d_in, const int* in_sizes, int n_in,
                              void* d_out, int out_size)
{
    const float* node_feat = (const float*)d_in[0];
    const float* edge_feat = (const float*)d_in[1];
    const int*   edge_index= (const int*)  d_in[2];
    const float* enW1=(const float*)d_in[3],  *enb1=(const float*)d_in[4];
    const float* enW2=(const float*)d_in[5],  *enb2=(const float*)d_in[6];
    const float* enW3=(const float*)d_in[7],  *enb3=(const float*)d_in[8];
    const float* enlg=(const float*)d_in[9],  *enlb=(const float*)d_in[10];
    const float* eeW1=(const float*)d_in[11], *eeb1=(const float*)d_in[12];
    const float* eeW2=(const float*)d_in[13], *eeb2=(const float*)d_in[14];
    const float* eeW3=(const float*)d_in[15], *eeb3=(const float*)d_in[16];
    const float* eelg=(const float*)d_in[17], *eelb=(const float*)d_in[18];
    const float* procW=(const float*)d_in[19], *procb=(const float*)d_in[20];
    const float* bng =(const float*)d_in[21], *bnb =(const float*)d_in[22];
    const float* dW1=(const float*)d_in[23], *db1=(const float*)d_in[24];
    const float* dW2=(const float*)d_in[25], *db2=(const float*)d_in[26];
    const float* dW3=(const float*)d_in[27], *db3=(const float*)d_in[28];
    const float* dlg=(const float*)d_in[29], *dlb=(const float*)d_in[30];
    float* out = (float*)d_out;

    const int* src = edge_index;
    const int* dst = edge_index + NE;

    float *p_hn,*p_h,*p_x,*p_eacc,*p_dis,*p_selfw,*p_ccoef,*p_bnsum,*p_bnsq;
    int *p_cnt,*p_deg,*p_off,*p_cur,*p_csrc;
    cudaGetSymbolAddress((void**)&p_hn,   g_hn);
    cudaGetSymbolAddress((void**)&p_h,    g_h);
    cudaGetSymbolAddress((void**)&p_x,    g_x);
    cudaGetSymbolAddress((void**)&p_eacc, g_eacc);
    cudaGetSymbolAddress((void**)&p_cnt,  g_cnt);
    cudaGetSymbolAddress((void**)&p_deg,  g_deg);
    cudaGetSymbolAddress((void**)&p_dis,  g_dis);
    cudaGetSymbolAddress((void**)&p_selfw,g_selfw);
    cudaGetSymbolAddress((void**)&p_off,  g_off);
    cudaGetSymbolAddress((void**)&p_cur,  g_cur);
    cudaGetSymbolAddress((void**)&p_csrc, g_csrc);
    cudaGetSymbolAddress((void**)&p_ccoef,g_ccoef);
    cudaGetSymbolAddress((void**)&p_bnsum,g_bnsum);
    cudaGetSymbolAddress((void**)&p_bnsq, g_bnsq);

    // MLP smem: sW2 16384 + buf 8448 + sIn 1280 + 3*128 + 64 = 26560 floats = 106240 B (2 CTAs/SM)
    const size_t MLP_SMEM  = (size_t)(16384 + 8448 + 1280 + 128 + 128 + 128 + 64) * 4;
    const size_t GEMM_SMEM = (size_t)(16384 + 8448 + 128 + 128) * 4;
    cudaFuncSetAttribute(mlp3_kernel<19,0>, cudaFuncAttributeMaxDynamicSharedMemorySize, (int)MLP_SMEM);
    cudaFuncSetAttribute(mlp3_kernel<4,1>,  cudaFuncAttributeMaxDynamicSharedMemorySize, (int)MLP_SMEM);
    cudaFuncSetAttribute(mlp3_kernel<128,2>,cudaFuncAttributeMaxDynamicSharedMemorySize, (int)MLP_SMEM);
    cudaFuncSetAttribute(gemm_kernel,       cudaFuncAttributeMaxDynamicSharedMemorySize, (int)GEMM_SMEM);

    const int NODE_TB = (NN + 63) / 64;        // 782
    const int EDGE_TB = NE / 64;               // 12500
    const int E_B256  = (NE + 255) / 256;
    const int N_B256  = (NN + 255) / 256;
    const int NV4_B   = (NN*32 + 255) / 256;
    const int AGG_B   = 1184;                  // 148 SMs * 8

    cudaMemsetAsync(p_eacc, 0, (size_t)NN*DD*sizeof(float));
    cudaMemsetAsync(p_cnt,  0, (size_t)NN*sizeof(int));
    cudaMemsetAsync(p_deg,  0, (size_t)NN*sizeof(int));
    deg_kernel<<<E_B256,256>>>(src, dst, p_deg, p_cnt);
    nodeprep_kernel<<<N_B256,256>>>(p_deg, p_dis, p_selfw);
    // node encoder
    mlp3_kernel<19,0><<<NODE_TB,256,MLP_SMEM>>>(node_feat, enW1,enb1,enW2,enb2,enW3,enb3,
                                                enlg,enlb, nullptr, p_hn, NN);
    // edge encoder  <-- ncu capture slot
    mlp3_kernel<4,1><<<EDGE_TB,256,MLP_SMEM>>>(edge_feat, eeW1,eeb1,eeW2,eeb2,eeW3,eeb3,
                                               eelg,eelb, src, p_eacc, NE);
    encfin_kernel<<<NV4_B,256>>>(p_hn, p_eacc, p_cnt);
    cudaMemsetAsync(p_cur, 0, (size_t)NN*sizeof(int));
    scan_kernel<<<1,1024>>>(p_deg, p_off);
    fill_kernel<<<E_B256,256>>>(src, dst, p_dis, p_off, p_cur, p_csrc, p_ccoef);

    for (int s = 0; s < NSTEPS; s++){
        const float* W0 = procW + (size_t)(s*2+0)*DD*DD;
        const float* W1 = procW + (size_t)(s*2+1)*DD*DD;
        const float* b0 = procb + (size_t)(s*2+0)*DD;
        const float* b1 = procb + (size_t)(s*2+1)*DD;

        gemm_kernel<<<NODE_TB,256,GEMM_SMEM>>>(p_hn, W0, p_h, NN,
                                               nullptr,nullptr,nullptr,nullptr, 0);
        cudaMemsetAsync(p_bnsum, 0, DD*sizeof(float));
        cudaMemsetAsync(p_bnsq,  0, DD*sizeof(float));
        agg_kernel<1><<<AGG_B,256>>>(p_h, p_off, p_csrc, p_ccoef, p_selfw, b0,
                                     p_x, nullptr, p_bnsum, p_bnsq);

        gemm_kernel<<<NODE_TB,256,GEMM_SMEM>>>(p_x, W1, p_h, NN,
                                               p_bnsum, p_bnsq,
                                               bng + (size_t)s*DD, bnb + (size_t)s*DD, 1);
        agg_kernel<2><<<AGG_B,256>>>(p_h, p_off, p_csrc, p_ccoef, p_selfw, b1,
                                     nullptr, p_hn, nullptr, nullptr);
    }

    mlp3_kernel<128,2><<<NODE_TB,256,MLP_SMEM>>>(p_hn, dW1,db1,dW2,db2,dW3,db3,
                                                 dlg,dlb, nullptr, out, NN);
    (void)in_sizes; (void)n_in; (void)out_size;
}